// round 13
// baseline (speedup 1.0000x reference)
#include <cuda_runtime.h>
#include <cuda_fp16.h>
#include <cstdint>

// ---------------- problem constants ----------------
#define BATCH   4
#define CIN     128
#define COUT    128
#define HDIM    128
#define WDIM    128
#define HW      (HDIM * WDIM)      // 16384
#define NGROUP  4
#define CG      32
#define KTAPS   9
#define RTOT    (CIN * KTAPS)      // 1152 = 72 * 16
#define NSTEP   72                 // k16 steps
#define TPX     32                 // pixels (N) per block
#define NTHREADS 256

// ---------------- smem layout (bytes) ----------------
// S (samples, f16 single plane): [1152 k][64 B swizzled row] = 73728
// misc @ 73728: ss0(128), ss1(128), swo(576)
#define SMEM_S_OFF   0
#define SMEM_MISC    73728
#define OFF_SS0      (SMEM_MISC + 0)
#define OFF_SS1      (SMEM_MISC + 128)
#define OFF_SWO      (SMEM_MISC + 256)
#define SMEM_BYTES   (SMEM_MISC + 832)   // 74560  (x3 CTAs = 223,680)

// Weights pre-packed in m16n8k16 A-fragment order, single f16 plane:
// uint4 idx = (step*8 + otile)*32 + lane
__device__ __align__(16) uint32_t g_wAf32[NSTEP * 8 * 32 * 4];   // 294912 B

// f16 copy of x, SAME [B,C,H,W] layout (halves gather bytes)
__device__ __align__(16) __half g_xh[BATCH * CIN * HW];          // 16.8 MB

__device__ __forceinline__ uint32_t smem_to_u32(const void* p) {
    uint32_t a;
    asm("{ .reg .u64 t; cvta.to.shared.u64 t, %1; cvt.u32.u64 %0, t; }" : "=r"(a) : "l"(p));
    return a;
}

// S swizzle: row k is 64B (32 px f16), 4 x 16B chunks; chunk ^= (k>>1)&3 so
// ldmatrix's 8-row phases hit disjoint 16B groups.
__device__ __forceinline__ int s_off(int k, int px) {
    return (k << 6) + ((px & 7) << 1) + ((((px >> 3) ^ ((k >> 1) & 3))) << 4);
}

__device__ __forceinline__ void ldsm_x4_trans(uint32_t* r, uint32_t addr) {
    asm volatile("ldmatrix.sync.aligned.m8n8.x4.trans.shared.b16 {%0,%1,%2,%3}, [%4];"
                 : "=r"(r[0]), "=r"(r[1]), "=r"(r[2]), "=r"(r[3]) : "r"(addr));
}
__device__ __forceinline__ void mma_f16(float* c, const uint32_t* a, uint32_t b0, uint32_t b1) {
    asm volatile(
        "mma.sync.aligned.m16n8k16.row.col.f32.f16.f16.f32 "
        "{%0,%1,%2,%3}, {%4,%5,%6,%7}, {%8,%9}, {%0,%1,%2,%3};"
        : "+f"(c[0]), "+f"(c[1]), "+f"(c[2]), "+f"(c[3])
        : "r"(a[0]), "r"(a[1]), "r"(a[2]), "r"(a[3]), "r"(b0), "r"(b1));
}

// ---------------- prep 0: x -> f16 same layout (streaming) ----------------
__global__ void prep_xh_kernel(const float* __restrict__ x) {
    int i = blockIdx.x * 256 + threadIdx.x;          // processes 4 floats
    const float4 v = reinterpret_cast<const float4*>(x)[i];
    __half2 a = __floats2half2_rn(v.x, v.y);
    __half2 b = __floats2half2_rn(v.z, v.w);
    uint32_t ua = *reinterpret_cast<uint32_t*>(&a);
    uint32_t ub = *reinterpret_cast<uint32_t*>(&b);
    reinterpret_cast<uint2*>(g_xh)[i] = make_uint2(ua, ub);
}

// ---------------- prep: weights -> A-fragment layout, f16 ----------------
__global__ void prep_wAf_kernel(const float* __restrict__ wd) {
    int idx = blockIdx.x * 256 + threadIdx.x;       // b32 index
    if (idx >= NSTEP * 8 * 32 * 4) return;
    int q     = idx & 3;
    int lane  = (idx >> 2) & 31;
    int ot    = (idx >> 7) & 7;
    int step  = idx >> 10;
    int g = lane >> 2, t = lane & 3;
    int row = ot * 16 + g + ((q & 1) << 3);
    int col = step * 16 + t * 2 + ((q >> 1) << 3);
    __half h0 = __float2half_rn(wd[row * RTOT + col]);
    __half h1 = __float2half_rn(wd[row * RTOT + col + 1]);
    g_wAf32[idx] = ((uint32_t)reinterpret_cast<unsigned short&>(h1) << 16)
                 |  (uint32_t)reinterpret_cast<unsigned short&>(h0);
}

// ---------------- main kernel ----------------
__global__ void __launch_bounds__(NTHREADS, 3)
deform_kernel(const float* __restrict__ x,        // unused (g_xh)
              const float* __restrict__ shape,    // [B,2,H,W]
              const float* __restrict__ w_offset, // [72][2]
              float* __restrict__ out)            // [B,COUT,H,W]
{
    extern __shared__ char smem[];
    const uint32_t smem_u32 = smem_to_u32(smem);
    float* ss0 = (float*)(smem + OFF_SS0);
    float* ss1 = (float*)(smem + OFF_SS1);
    float* swo = (float*)(smem + OFF_SWO);

    const int tid = threadIdx.x;
    const int wid = tid >> 5;
    const int lid = tid & 31;

    const int b   = blockIdx.x >> 9;
    const int rem = blockIdx.x & 511;
    const int h   = rem >> 2;
    const int w0  = (rem & 3) << 5;

    // ---- stage small tables ----
    if (tid < 32)                     ss0[tid]     = shape[(size_t)(b*2+0)*HW + h*WDIM + w0 + tid];
    else if (tid < 64)                ss1[tid-32]  = shape[(size_t)(b*2+1)*HW + h*WDIM + w0 + (tid-32)];
    else if (tid >= 64 && tid < 208)  swo[tid-64]  = w_offset[tid-64];
    __syncthreads();

    // ---- phase A: sample (f16 source) -> f16 into swizzled S [1152][32] ----
    for (int i = tid; i < 36 * TPX; i += NTHREADS) {
        int gk = i >> 5, px = i & 31;
        int g  = gk / 9, k = gk - g * 9;
        int ky = k / 3,  kx = k - ky * 3;
        float s0 = ss0[px], s1 = ss1[px];
        float offy = swo[gk*4 + 0] * s0 + swo[gk*4 + 1] * s1;
        float offx = swo[gk*4 + 2] * s0 + swo[gk*4 + 3] * s1;
        float py  = offy + (float)(ky - 1 + h);
        float pxf = offx + (float)(kx - 1 + w0 + px);
        float y0f = floorf(py), x0f = floorf(pxf);
        float fy = py - y0f, fx = pxf - x0f;
        int y0 = (int)y0f, x0 = (int)x0f;

        float aw[4]; int ai[4];
        #pragma unroll
        for (int t = 0; t < 4; t++) {
            int dy = t >> 1, dx = t & 1;
            int yi = y0 + dy, xi = x0 + dx;
            bool valid = (yi >= 0) && (yi < HDIM) && (xi >= 0) && (xi < WDIM);
            float wy = dy ? fy : 1.0f - fy;
            float wx = dx ? fx : 1.0f - fx;
            int yc = min(max(yi, 0), HDIM - 1);
            int xc = min(max(xi, 0), WDIM - 1);
            aw[t] = valid ? (wy * wx) : 0.0f;
            ai[t] = yc * WDIM + xc;
        }

        const __half* xb = g_xh + ((size_t)b * CIN + g * CG) * HW;
        const int r0 = (g * CG) * KTAPS + k;     // r for cg=0; stride 9 per cg
        #pragma unroll 4
        for (int cg = 0; cg < CG; cg++) {
            const __half* xc = xb + (size_t)cg * HW;
            float v = aw[0]*__half2float(xc[ai[0]]) + aw[1]*__half2float(xc[ai[1]])
                    + aw[2]*__half2float(xc[ai[2]]) + aw[3]*__half2float(xc[ai[3]]);
            int r  = r0 + cg * KTAPS;
            *(__half*)(smem + SMEM_S_OFF + s_off(r, px)) = __float2half_rn(v);
        }
    }
    __syncthreads();

    // ---- phase B: 8 warps, each o16 x n32, 2-stage software pipeline ----
    const int ot    = wid;               // o = wid*16 .. +15
    const int bkrow = lid & 15;
    const int bsel  = lid >> 4;

    const uint4* gA = reinterpret_cast<const uint4*>(g_wAf32);

    float acc[4][4];
    #pragma unroll
    for (int a2 = 0; a2 < 4; a2++)
        #pragma unroll
        for (int a3 = 0; a3 < 4; a3++) acc[a2][a3] = 0.0f;

    uint32_t bf0[2][4], bf1[2][4];

#define LOAD_B(buf, stepv) do {                                                  \
        const int _k = ((stepv) << 4) + bkrow;                                   \
        _Pragma("unroll")                                                        \
        for (int _half = 0; _half < 2; _half++) {                                \
            int _bnchk = (_half << 1) + bsel;                                    \
            int _boff  = (_k << 6) + (((_bnchk ^ ((_k >> 1) & 3))) << 4);        \
            ldsm_x4_trans(buf[_half], smem_u32 + SMEM_S_OFF + (uint32_t)_boff);  \
        }                                                                        \
    } while (0)

#define MMA4(Areg, buf) do {                                                     \
        const uint32_t* _a = (const uint32_t*)&(Areg);                           \
        mma_f16(acc[0], _a, buf[0][0], buf[0][1]);                               \
        mma_f16(acc[1], _a, buf[0][2], buf[0][3]);                               \
        mma_f16(acc[2], _a, buf[1][0], buf[1][1]);                               \
        mma_f16(acc[3], _a, buf[1][2], buf[1][3]);                               \
    } while (0)

    uint4 A0 = gA[(ot << 5) + lid];          // step 0
    LOAD_B(bf0, 0);

    for (int s = 0; s < NSTEP; s += 2) {
        uint4 A1 = gA[(((s + 1) * 8 + ot) << 5) + lid];
        LOAD_B(bf1, s + 1);

        MMA4(A0, bf0);

        uint4 A2 = A1;
        if (s + 2 < NSTEP) {
            A2 = gA[(((s + 2) * 8 + ot) << 5) + lid];
            LOAD_B(bf0, s + 2);
        }

        MMA4(A1, bf1);

        A0 = A2;
    }
#undef LOAD_B
#undef MMA4

    // ---- epilogue: acc -> ReLU -> gmem ----
    const int g = lid >> 2, t = lid & 3;
    #pragma unroll
    for (int j = 0; j < 4; j++) {
        int o  = (wid << 4) + g;
        int px = (j << 3) + (t << 1);
        float* op0 = out + (((size_t)b * COUT + o) << 14) + (h << 7) + w0 + px;
        float* op1 = op0 + ((size_t)8 << 14);   // row o+8
        float2 v0 = { fmaxf(acc[j][0], 0.0f), fmaxf(acc[j][1], 0.0f) };
        float2 v1 = { fmaxf(acc[j][2], 0.0f), fmaxf(acc[j][3], 0.0f) };
        *reinterpret_cast<float2*>(op0) = v0;
        *reinterpret_cast<float2*>(op1) = v1;
    }
}

extern "C" void kernel_launch(void* const* d_in, const int* in_sizes, int n_in,
                              void* d_out, int out_size) {
    const float* x        = (const float*)d_in[0];
    const float* shape    = (const float*)d_in[1];
    const float* w_offset = (const float*)d_in[2];
    const float* w_deform = (const float*)d_in[3];
    float* out = (float*)d_out;

    cudaFuncSetAttribute(deform_kernel,
                         cudaFuncAttributeMaxDynamicSharedMemorySize, SMEM_BYTES);

    prep_xh_kernel<<<(BATCH * CIN * HW / 4) / 256, 256>>>(x);
    prep_wAf_kernel<<<(NSTEP * 8 * 32 * 4 + 255) / 256, 256>>>(w_deform);

    const int nblocks = BATCH * HDIM * (WDIM / TPX);   // 2048
    deform_kernel<<<nblocks, NTHREADS, SMEM_BYTES>>>(x, shape, w_offset, out);
}

// round 14
// speedup vs baseline: 1.0745x; 1.0745x over previous
#include <cuda_runtime.h>
#include <cuda_fp16.h>
#include <cstdint>

// ---------------- problem constants ----------------
#define BATCH   4
#define CIN     128
#define COUT    128
#define HDIM    128
#define WDIM    128
#define HW      (HDIM * WDIM)      // 16384
#define NGROUP  4
#define CG      32
#define KTAPS   9
#define RTOT    (CIN * KTAPS)      // 1152 = 72 * 16
#define NSTEP   72                 // k16 steps
#define HSTEP   36                 // steps per k-half
#define TPX     32                 // pixels (N) per block
#define NTHREADS 256

// ---------------- smem layout (bytes) ----------------
// S (samples, f16 single plane): [1152 k][64 B swizzled row] = 73728
// sacc (partial fp32 accs) aliases S after GEMM: 128 x 33 floats = 16896 B
// misc @ 73728: ss0(128), ss1(128), swo(576)
#define SMEM_S_OFF   0
#define SMEM_MISC    73728
#define OFF_SS0      (SMEM_MISC + 0)
#define OFF_SS1      (SMEM_MISC + 128)
#define OFF_SWO      (SMEM_MISC + 256)
#define SMEM_BYTES   (SMEM_MISC + 832)   // 74560  (x3 CTAs = 223,680)
#define SACC_STRIDE  33

// Weights pre-packed in m16n8k16 A-fragment order, single f16 plane:
// uint4 idx = (step*8 + otile)*32 + lane
__device__ __align__(16) uint32_t g_wAf32[NSTEP * 8 * 32 * 4];   // 294912 B

__device__ __forceinline__ uint32_t smem_to_u32(const void* p) {
    uint32_t a;
    asm("{ .reg .u64 t; cvta.to.shared.u64 t, %1; cvt.u32.u64 %0, t; }" : "=r"(a) : "l"(p));
    return a;
}

// S swizzle: row k is 64B (32 px f16), 4 x 16B chunks; chunk ^= (k>>1)&3 so
// ldmatrix's 8-row phases hit disjoint 16B groups.
__device__ __forceinline__ int s_off(int k, int px) {
    return (k << 6) + ((px & 7) << 1) + ((((px >> 3) ^ ((k >> 1) & 3))) << 4);
}

__device__ __forceinline__ void ldsm_x4_trans(uint32_t* r, uint32_t addr) {
    asm volatile("ldmatrix.sync.aligned.m8n8.x4.trans.shared.b16 {%0,%1,%2,%3}, [%4];"
                 : "=r"(r[0]), "=r"(r[1]), "=r"(r[2]), "=r"(r[3]) : "r"(addr));
}
__device__ __forceinline__ void mma_f16(float* c, const uint32_t* a, uint32_t b0, uint32_t b1) {
    asm volatile(
        "mma.sync.aligned.m16n8k16.row.col.f32.f16.f16.f32 "
        "{%0,%1,%2,%3}, {%4,%5,%6,%7}, {%8,%9}, {%0,%1,%2,%3};"
        : "+f"(c[0]), "+f"(c[1]), "+f"(c[2]), "+f"(c[3])
        : "r"(a[0]), "r"(a[1]), "r"(a[2]), "r"(a[3]), "r"(b0), "r"(b1));
}

// ---------------- prep: weights -> A-fragment layout, f16 ----------------
__global__ void prep_wAf_kernel(const float* __restrict__ wd) {
    int idx = blockIdx.x * 256 + threadIdx.x;       // b32 index
    if (idx >= NSTEP * 8 * 32 * 4) return;
    int q     = idx & 3;
    int lane  = (idx >> 2) & 31;
    int ot    = (idx >> 7) & 7;
    int step  = idx >> 10;
    int g = lane >> 2, t = lane & 3;
    int row = ot * 16 + g + ((q & 1) << 3);
    int col = step * 16 + t * 2 + ((q >> 1) << 3);
    __half h0 = __float2half_rn(wd[row * RTOT + col]);
    __half h1 = __float2half_rn(wd[row * RTOT + col + 1]);
    g_wAf32[idx] = ((uint32_t)reinterpret_cast<unsigned short&>(h1) << 16)
                 |  (uint32_t)reinterpret_cast<unsigned short&>(h0);
}

// ---------------- main kernel ----------------
__global__ void __launch_bounds__(NTHREADS, 3)
deform_kernel(const float* __restrict__ x,        // [B,C,H,W]
              const float* __restrict__ shape,    // [B,2,H,W]
              const float* __restrict__ w_offset, // [72][2]
              float* __restrict__ out)            // [B,COUT,H,W]
{
    extern __shared__ char smem[];
    const uint32_t smem_u32 = smem_to_u32(smem);
    float* ss0  = (float*)(smem + OFF_SS0);
    float* ss1  = (float*)(smem + OFF_SS1);
    float* swo  = (float*)(smem + OFF_SWO);
    float* sacc = (float*)(smem + SMEM_S_OFF);   // alias of S, used after GEMM

    const int tid = threadIdx.x;
    const int wid = tid >> 5;
    const int lid = tid & 31;

    const int b   = blockIdx.x >> 9;
    const int rem = blockIdx.x & 511;
    const int h   = rem >> 2;
    const int w0  = (rem & 3) << 5;

    // ---- stage small tables ----
    if (tid < 32)                     ss0[tid]     = shape[(size_t)(b*2+0)*HW + h*WDIM + w0 + tid];
    else if (tid < 64)                ss1[tid-32]  = shape[(size_t)(b*2+1)*HW + h*WDIM + w0 + (tid-32)];
    else if (tid >= 64 && tid < 208)  swo[tid-64]  = w_offset[tid-64];
    __syncthreads();

    // ---- phase A: sample -> f16 into swizzled S [1152][32] (all 8 warps) ----
    for (int i = tid; i < 36 * TPX; i += NTHREADS) {
        int gk = i >> 5, px = i & 31;
        int g  = gk / 9, k = gk - g * 9;
        int ky = k / 3,  kx = k - ky * 3;
        float s0 = ss0[px], s1 = ss1[px];
        float offy = swo[gk*4 + 0] * s0 + swo[gk*4 + 1] * s1;
        float offx = swo[gk*4 + 2] * s0 + swo[gk*4 + 3] * s1;
        float py  = offy + (float)(ky - 1 + h);
        float pxf = offx + (float)(kx - 1 + w0 + px);
        float y0f = floorf(py), x0f = floorf(pxf);
        float fy = py - y0f, fx = pxf - x0f;
        int y0 = (int)y0f, x0 = (int)x0f;

        float aw[4]; int ai[4];
        #pragma unroll
        for (int t = 0; t < 4; t++) {
            int dy = t >> 1, dx = t & 1;
            int yi = y0 + dy, xi = x0 + dx;
            bool valid = (yi >= 0) && (yi < HDIM) && (xi >= 0) && (xi < WDIM);
            float wy = dy ? fy : 1.0f - fy;
            float wx = dx ? fx : 1.0f - fx;
            int yc = min(max(yi, 0), HDIM - 1);
            int xc = min(max(xi, 0), WDIM - 1);
            aw[t] = valid ? (wy * wx) : 0.0f;
            ai[t] = yc * WDIM + xc;
        }

        const float* xb = x + ((size_t)b * CIN + g * CG) * HW;
        const int r0 = (g * CG) * KTAPS + k;     // r for cg=0; stride 9 per cg
        #pragma unroll 4
        for (int cg = 0; cg < CG; cg++) {
            const float* xc = xb + (size_t)cg * HW;
            float v = aw[0]*xc[ai[0]] + aw[1]*xc[ai[1]] + aw[2]*xc[ai[2]] + aw[3]*xc[ai[3]];
            int r  = r0 + cg * KTAPS;
            *(__half*)(smem + SMEM_S_OFF + s_off(r, px)) = __float2half_rn(v);
        }
    }
    __syncthreads();

    // ---- phase B: 8 warps = 2 k-halves x 4 o-quarters, tile o32 x n32 ----
    const int kw    = wid >> 2;          // k-half
    const int ow    = wid & 3;           // o-quarter (o = ow*32 .. +31)
    const int bkrow = lid & 15;
    const int bsel  = lid >> 4;

    const uint4* gA = reinterpret_cast<const uint4*>(g_wAf32);

    float acc[2][4][4];
    #pragma unroll
    for (int a1 = 0; a1 < 2; a1++)
        #pragma unroll
        for (int a2 = 0; a2 < 4; a2++)
            #pragma unroll
            for (int a3 = 0; a3 < 4; a3++) acc[a1][a2][a3] = 0.0f;

    const int step0 = kw * HSTEP;
    for (int s = 0; s < HSTEP; s++) {
        const int step = step0 + s;

        // A fragments for this warp's two otiles (no prefetch regs — R12
        // showed pipelining is free of benefit; keep register file small)
        uint4 A0 = gA[((step * 8 + (ow << 1) + 0) << 5) + lid];
        uint4 A1 = gA[((step * 8 + (ow << 1) + 1) << 5) + lid];

        // B fragments: two n16 halves
        const int k = (step << 4) + bkrow;
        uint32_t bf[2][4];
        #pragma unroll
        for (int half = 0; half < 2; half++) {
            int bnchk = (half << 1) + bsel;
            int boff  = (k << 6) + (((bnchk ^ ((k >> 1) & 3))) << 4);
            ldsm_x4_trans(bf[half], smem_u32 + SMEM_S_OFF + (uint32_t)boff);
        }

        // 8 MMAs: 2 otiles x 4 n8 tiles
        const uint32_t* a0 = (const uint32_t*)&A0;
        const uint32_t* a1 = (const uint32_t*)&A1;
        mma_f16(acc[0][0], a0, bf[0][0], bf[0][1]);
        mma_f16(acc[0][1], a0, bf[0][2], bf[0][3]);
        mma_f16(acc[0][2], a0, bf[1][0], bf[1][1]);
        mma_f16(acc[0][3], a0, bf[1][2], bf[1][3]);
        mma_f16(acc[1][0], a1, bf[0][0], bf[0][1]);
        mma_f16(acc[1][1], a1, bf[0][2], bf[0][3]);
        mma_f16(acc[1][2], a1, bf[1][0], bf[1][1]);
        mma_f16(acc[1][3], a1, bf[1][2], bf[1][3]);
    }
    __syncthreads();    // all LDSM from S done; S now reusable as sacc

    // ---- reduction: kw==1 dumps partials; kw==0 adds + ReLU + stores ----
    const int g = lid >> 2, t = lid & 3;
    if (kw == 1) {
        #pragma unroll
        for (int ot = 0; ot < 2; ot++) {
            #pragma unroll
            for (int j = 0; j < 4; j++) {
                int o  = (ow << 5) + (ot << 4) + g;
                int px = (j & 1) * 16 + (j >> 1) * 8 + (t << 1);  // j order-free
                // match acc layout: acc[ot][j] covers n8 tile j with
                // px = (j>>1)*16 + (j&1)*8  — recompute properly:
                px = ((j >> 1) << 4) + ((j & 1) << 3) + (t << 1);
                sacc[ o      * SACC_STRIDE + px    ] = acc[ot][j][0];
                sacc[ o      * SACC_STRIDE + px + 1] = acc[ot][j][1];
                sacc[(o + 8) * SACC_STRIDE + px    ] = acc[ot][j][2];
                sacc[(o + 8) * SACC_STRIDE + px + 1] = acc[ot][j][3];
            }
        }
    }
    __syncthreads();
    if (kw == 0) {
        #pragma unroll
        for (int ot = 0; ot < 2; ot++) {
            #pragma unroll
            for (int j = 0; j < 4; j++) {
                int o  = (ow << 5) + (ot << 4) + g;
                int px = ((j >> 1) << 4) + ((j & 1) << 3) + (t << 1);
                float* op0 = out + (((size_t)b * COUT + o) << 14) + (h << 7) + w0 + px;
                float* op1 = op0 + ((size_t)8 << 14);   // row o+8
                float2 v0, v1;
                v0.x = fmaxf(acc[ot][j][0] + sacc[ o      * SACC_STRIDE + px    ], 0.0f);
                v0.y = fmaxf(acc[ot][j][1] + sacc[ o      * SACC_STRIDE + px + 1], 0.0f);
                v1.x = fmaxf(acc[ot][j][2] + sacc[(o + 8) * SACC_STRIDE + px    ], 0.0f);
                v1.y = fmaxf(acc[ot][j][3] + sacc[(o + 8) * SACC_STRIDE + px + 1], 0.0f);
                *reinterpret_cast<float2*>(op0) = v0;
                *reinterpret_cast<float2*>(op1) = v1;
            }
        }
    }
}

extern "C" void kernel_launch(void* const* d_in, const int* in_sizes, int n_in,
                              void* d_out, int out_size) {
    const float* x        = (const float*)d_in[0];
    const float* shape    = (const float*)d_in[1];
    const float* w_offset = (const float*)d_in[2];
    const float* w_deform = (const float*)d_in[3];
    float* out = (float*)d_out;

    cudaFuncSetAttribute(deform_kernel,
                         cudaFuncAttributeMaxDynamicSharedMemorySize, SMEM_BYTES);

    prep_wAf_kernel<<<(NSTEP * 8 * 32 * 4 + 255) / 256, 256>>>(w_deform);

    const int nblocks = BATCH * HDIM * (WDIM / TPX);   // 2048
    deform_kernel<<<nblocks, NTHREADS, SMEM_BYTES>>>(x, shape, w_offset, out);
}

// round 15
// speedup vs baseline: 1.1081x; 1.0312x over previous
#include <cuda_runtime.h>
#include <cuda_fp16.h>
#include <cstdint>

// ---------------- problem constants ----------------
#define BATCH   4
#define CIN     128
#define COUT    128
#define HDIM    128
#define WDIM    128
#define HW      (HDIM * WDIM)      // 16384
#define NGROUP  4
#define CG      32
#define KTAPS   9
#define RTOT    (CIN * KTAPS)      // 1152 = 72 * 16
#define NSTEP   72                 // k16 steps
#define HSTEP   36                 // steps per k-half
#define TPX     32                 // pixels (N) per block
#define NTHREADS 256
#define XTOTAL  (BATCH * CIN * HW) // 8388608

// ---------------- smem layout (bytes) ----------------
// S (samples, f16 single plane): [1152 k][64 B swizzled row] = 73728
// sacc (partial fp32 accs) aliases S after GEMM: 128 x 33 floats
// misc @ 73728: ss0(128), ss1(128), swo(576)
#define SMEM_S_OFF   0
#define SMEM_MISC    73728
#define OFF_SS0      (SMEM_MISC + 0)
#define OFF_SS1      (SMEM_MISC + 128)
#define OFF_SWO      (SMEM_MISC + 256)
#define SMEM_BYTES   (SMEM_MISC + 832)   // 74560  (x3 CTAs = 223,680)
#define SACC_STRIDE  33

// Weights pre-packed in m16n8k16 A-fragment order, single f16 plane:
// uint4 idx = (step*8 + otile)*32 + lane
__device__ __align__(16) uint32_t g_wAf32[NSTEP * 8 * 32 * 4];   // 294912 B

// Pre-paired f16 copy of x: g_xp[i] = half2(x[i], x[i+1]).
// One 4B-aligned u32 load covers both x-corners of a bilinear row.
__device__ __align__(16) uint32_t g_xp[XTOTAL];                  // 33.5 MB

__device__ __forceinline__ uint32_t smem_to_u32(const void* p) {
    uint32_t a;
    asm("{ .reg .u64 t; cvta.to.shared.u64 t, %1; cvt.u32.u64 %0, t; }" : "=r"(a) : "l"(p));
    return a;
}

// S swizzle: row k is 64B (32 px f16), 4 x 16B chunks; chunk ^= (k>>1)&3 so
// ldmatrix's 8-row phases hit disjoint 16B groups.
__device__ __forceinline__ int s_off(int k, int px) {
    return (k << 6) + ((px & 7) << 1) + ((((px >> 3) ^ ((k >> 1) & 3))) << 4);
}

__device__ __forceinline__ void ldsm_x4_trans(uint32_t* r, uint32_t addr) {
    asm volatile("ldmatrix.sync.aligned.m8n8.x4.trans.shared.b16 {%0,%1,%2,%3}, [%4];"
                 : "=r"(r[0]), "=r"(r[1]), "=r"(r[2]), "=r"(r[3]) : "r"(addr));
}
__device__ __forceinline__ void mma_f16(float* c, const uint32_t* a, uint32_t b0, uint32_t b1) {
    asm volatile(
        "mma.sync.aligned.m16n8k16.row.col.f32.f16.f16.f32 "
        "{%0,%1,%2,%3}, {%4,%5,%6,%7}, {%8,%9}, {%0,%1,%2,%3};"
        : "+f"(c[0]), "+f"(c[1]), "+f"(c[2]), "+f"(c[3])
        : "r"(a[0]), "r"(a[1]), "r"(a[2]), "r"(a[3]), "r"(b0), "r"(b1));
}

__device__ __forceinline__ uint32_t pack_h2(float a, float b) {
    __half2 h = __floats2half2_rn(a, b);
    return *reinterpret_cast<uint32_t*>(&h);
}

// ---------------- prep 0: x -> adjacent-pair f16 array ----------------
// thread t covers elements [4t, 4t+3]; pair j = (x[4t+j], x[4t+j+1])
__global__ void prep_xp_kernel(const float* __restrict__ x) {
    size_t t = (size_t)blockIdx.x * 256 + threadIdx.x;   // 2,097,152 threads
    size_t base = t * 4;
    const float4 v = reinterpret_cast<const float4*>(x)[t];
    float nxt = (base + 4 < XTOTAL) ? x[base + 4] : 0.0f;
    uint4 o;
    o.x = pack_h2(v.x, v.y);
    o.y = pack_h2(v.y, v.z);
    o.z = pack_h2(v.z, v.w);
    o.w = pack_h2(v.w, nxt);
    reinterpret_cast<uint4*>(g_xp)[t] = o;
}

// ---------------- prep: weights -> A-fragment layout, f16 ----------------
__global__ void prep_wAf_kernel(const float* __restrict__ wd) {
    int idx = blockIdx.x * 256 + threadIdx.x;       // b32 index
    if (idx >= NSTEP * 8 * 32 * 4) return;
    int q     = idx & 3;
    int lane  = (idx >> 2) & 31;
    int ot    = (idx >> 7) & 7;
    int step  = idx >> 10;
    int g = lane >> 2, t = lane & 3;
    int row = ot * 16 + g + ((q & 1) << 3);
    int col = step * 16 + t * 2 + ((q >> 1) << 3);
    __half h0 = __float2half_rn(wd[row * RTOT + col]);
    __half h1 = __float2half_rn(wd[row * RTOT + col + 1]);
    g_wAf32[idx] = ((uint32_t)reinterpret_cast<unsigned short&>(h1) << 16)
                 |  (uint32_t)reinterpret_cast<unsigned short&>(h0);
}

// ---------------- main kernel ----------------
__global__ void __launch_bounds__(NTHREADS, 3)
deform_kernel(const float* __restrict__ x,        // unused (g_xp)
              const float* __restrict__ shape,    // [B,2,H,W]
              const float* __restrict__ w_offset, // [72][2]
              float* __restrict__ out)            // [B,COUT,H,W]
{
    extern __shared__ char smem[];
    const uint32_t smem_u32 = smem_to_u32(smem);
    float* ss0  = (float*)(smem + OFF_SS0);
    float* ss1  = (float*)(smem + OFF_SS1);
    float* swo  = (float*)(smem + OFF_SWO);
    float* sacc = (float*)(smem + SMEM_S_OFF);   // alias of S, used after GEMM

    const int tid = threadIdx.x;
    const int wid = tid >> 5;
    const int lid = tid & 31;

    const int b   = blockIdx.x >> 9;
    const int rem = blockIdx.x & 511;
    const int h   = rem >> 2;
    const int w0  = (rem & 3) << 5;

    // ---- stage small tables ----
    if (tid < 32)                     ss0[tid]     = shape[(size_t)(b*2+0)*HW + h*WDIM + w0 + tid];
    else if (tid < 64)                ss1[tid-32]  = shape[(size_t)(b*2+1)*HW + h*WDIM + w0 + (tid-32)];
    else if (tid >= 64 && tid < 208)  swo[tid-64]  = w_offset[tid-64];
    __syncthreads();

    // ---- phase A: sample via paired loads -> f16 swizzled S [1152][32] ----
    for (int i = tid; i < 36 * TPX; i += NTHREADS) {
        int gk = i >> 5, px = i & 31;
        int g  = gk / 9, k = gk - g * 9;
        int ky = k / 3,  kx = k - ky * 3;
        float s0 = ss0[px], s1 = ss1[px];
        float offy = swo[gk*4 + 0] * s0 + swo[gk*4 + 1] * s1;
        float offx = swo[gk*4 + 2] * s0 + swo[gk*4 + 3] * s1;
        float py  = offy + (float)(ky - 1 + h);
        float pxf = offx + (float)(kx - 1 + w0 + px);
        float y0f = floorf(py), x0f = floorf(pxf);
        float fy = py - y0f, fx = pxf - x0f;
        int y0 = (int)y0f, x0 = (int)x0f;

        // per-row y weights (zeroed when row out of bounds)
        float wy0 = (y0     >= 0 && y0     <= 127) ? (1.0f - fy) : 0.0f;
        float wy1 = (y0 + 1 >= 0 && y0 + 1 <= 127) ? fy          : 0.0f;
        int yc0 = min(max(y0,     0), 127);
        int yc1 = min(max(y0 + 1, 0), 127);

        // x-pair weights: one u32 pair at xb covers both x-corners
        int xb = min(max(x0, 0), 126);
        float wl, wr;
        if (x0 >= 0 && x0 <= 126)      { wl = 1.0f - fx; wr = fx;          }
        else if (x0 == -1)             { wl = fx;        wr = 0.0f;        }
        else if (x0 == 127)            { wl = 0.0f;      wr = 1.0f - fx;   }
        else                           { wl = 0.0f;      wr = 0.0f;        }

        float w00 = wy0 * wl, w01 = wy0 * wr;
        float w10 = wy1 * wl, w11 = wy1 * wr;
        int i0 = yc0 * WDIM + xb;
        int i1 = yc1 * WDIM + xb;

        const uint32_t* xpb = g_xp + ((size_t)b * CIN + g * CG) * HW;
        const int r0 = (g * CG) * KTAPS + k;     // r for cg=0; stride 9 per cg
        #pragma unroll 4
        for (int cg = 0; cg < CG; cg++) {
            const uint32_t* xc = xpb + (size_t)cg * HW;
            __half2 p0h = *reinterpret_cast<const __half2*>(xc + i0);
            __half2 p1h = *reinterpret_cast<const __half2*>(xc + i1);
            float2 f0 = __half22float2(p0h);
            float2 f1 = __half22float2(p1h);
            float v = w00 * f0.x + w01 * f0.y + w10 * f1.x + w11 * f1.y;
            int r  = r0 + cg * KTAPS;
            *(__half*)(smem + SMEM_S_OFF + s_off(r, px)) = __float2half_rn(v);
        }
    }
    __syncthreads();

    // ---- phase B: 8 warps = 2 k-halves x 4 o-quarters, tile o32 x n32 ----
    const int kw    = wid >> 2;          // k-half
    const int ow    = wid & 3;           // o-quarter (o = ow*32 .. +31)
    const int bkrow = lid & 15;
    const int bsel  = lid >> 4;

    const uint4* gA = reinterpret_cast<const uint4*>(g_wAf32);

    float acc[2][4][4];
    #pragma unroll
    for (int a1 = 0; a1 < 2; a1++)
        #pragma unroll
        for (int a2 = 0; a2 < 4; a2++)
            #pragma unroll
            for (int a3 = 0; a3 < 4; a3++) acc[a1][a2][a3] = 0.0f;

    const int step0 = kw * HSTEP;
    for (int s = 0; s < HSTEP; s++) {
        const int step = step0 + s;

        uint4 A0 = gA[((step * 8 + (ow << 1) + 0) << 5) + lid];
        uint4 A1 = gA[((step * 8 + (ow << 1) + 1) << 5) + lid];

        const int k = (step << 4) + bkrow;
        uint32_t bf[2][4];
        #pragma unroll
        for (int half = 0; half < 2; half++) {
            int bnchk = (half << 1) + bsel;
            int boff  = (k << 6) + (((bnchk ^ ((k >> 1) & 3))) << 4);
            ldsm_x4_trans(bf[half], smem_u32 + SMEM_S_OFF + (uint32_t)boff);
        }

        const uint32_t* a0 = (const uint32_t*)&A0;
        const uint32_t* a1 = (const uint32_t*)&A1;
        mma_f16(acc[0][0], a0, bf[0][0], bf[0][1]);
        mma_f16(acc[0][1], a0, bf[0][2], bf[0][3]);
        mma_f16(acc[0][2], a0, bf[1][0], bf[1][1]);
        mma_f16(acc[0][3], a0, bf[1][2], bf[1][3]);
        mma_f16(acc[1][0], a1, bf[0][0], bf[0][1]);
        mma_f16(acc[1][1], a1, bf[0][2], bf[0][3]);
        mma_f16(acc[1][2], a1, bf[1][0], bf[1][1]);
        mma_f16(acc[1][3], a1, bf[1][2], bf[1][3]);
    }
    __syncthreads();    // all LDSM from S done; S now reusable as sacc

    // ---- reduction: kw==1 dumps partials; kw==0 adds + ReLU + stores ----
    // acc[ot][j] covers n8 tile j at px = j*8 (j = half*2 + sub)
    const int g = lid >> 2, t = lid & 3;
    if (kw == 1) {
        #pragma unroll
        for (int ot = 0; ot < 2; ot++) {
            #pragma unroll
            for (int j = 0; j < 4; j++) {
                int o  = (ow << 5) + (ot << 4) + g;
                int px = (j << 3) + (t << 1);
                sacc[ o      * SACC_STRIDE + px    ] = acc[ot][j][0];
                sacc[ o      * SACC_STRIDE + px + 1] = acc[ot][j][1];
                sacc[(o + 8) * SACC_STRIDE + px    ] = acc[ot][j][2];
                sacc[(o + 8) * SACC_STRIDE + px + 1] = acc[ot][j][3];
            }
        }
    }
    __syncthreads();
    if (kw == 0) {
        #pragma unroll
        for (int ot = 0; ot < 2; ot++) {
            #pragma unroll
            for (int j = 0; j < 4; j++) {
                int o  = (ow << 5) + (ot << 4) + g;
                int px = (j << 3) + (t << 1);
                float* op0 = out + (((size_t)b * COUT + o) << 14) + (h << 7) + w0 + px;
                float* op1 = op0 + ((size_t)8 << 14);   // row o+8
                float2 v0, v1;
                v0.x = fmaxf(acc[ot][j][0] + sacc[ o      * SACC_STRIDE + px    ], 0.0f);
                v0.y = fmaxf(acc[ot][j][1] + sacc[ o      * SACC_STRIDE + px + 1], 0.0f);
                v1.x = fmaxf(acc[ot][j][2] + sacc[(o + 8) * SACC_STRIDE + px    ], 0.0f);
                v1.y = fmaxf(acc[ot][j][3] + sacc[(o + 8) * SACC_STRIDE + px + 1], 0.0f);
                *reinterpret_cast<float2*>(op0) = v0;
                *reinterpret_cast<float2*>(op1) = v1;
            }
        }
    }
}

extern "C" void kernel_launch(void* const* d_in, const int* in_sizes, int n_in,
                              void* d_out, int out_size) {
    const float* x        = (const float*)d_in[0];
    const float* shape    = (const float*)d_in[1];
    const float* w_offset = (const float*)d_in[2];
    const float* w_deform = (const float*)d_in[3];
    float* out = (float*)d_out;

    cudaFuncSetAttribute(deform_kernel,
                         cudaFuncAttributeMaxDynamicSharedMemorySize, SMEM_BYTES);

    prep_xp_kernel<<<(XTOTAL / 4) / 256, 256>>>(x);
    prep_wAf_kernel<<<(NSTEP * 8 * 32 * 4 + 255) / 256, 256>>>(w_deform);

    const int nblocks = BATCH * HDIM * (WDIM / TPX);   // 2048
    deform_kernel<<<nblocks, NTHREADS, SMEM_BYTES>>>(x, shape, w_offset, out);
}

// round 16
// speedup vs baseline: 1.2615x; 1.1385x over previous
#include <cuda_runtime.h>
#include <cuda_fp16.h>
#include <cstdint>

// ---------------- problem constants ----------------
#define BATCH   4
#define CIN     128
#define COUT    128
#define HDIM    128
#define WDIM    128
#define HW      (HDIM * WDIM)      // 16384
#define NGROUP  4
#define CG      32
#define KTAPS   9
#define RTOT    (CIN * KTAPS)      // 1152 = 72 * 16
#define NSTEP   72                 // k16 steps
#define HSTEP   36                 // steps per k-half
#define TPX     32                 // pixels (N) per block
#define NTHREADS 256
#define NPAIRS  (BATCH * (CIN / 2))            // 256 channel pairs
#define XQ_U64  ((size_t)NPAIRS * HW)          // 4,194,304 u64 entries

// ---------------- smem layout (bytes) ----------------
// S (samples, f16 single plane): [1152 k][64 B swizzled row] = 73728
// sacc (partial fp32 accs) aliases S after GEMM: 128 x 33 floats
// misc @ 73728: ss0(128), ss1(128), swo(576)
#define SMEM_S_OFF   0
#define SMEM_MISC    73728
#define OFF_SS0      (SMEM_MISC + 0)
#define OFF_SS1      (SMEM_MISC + 128)
#define OFF_SWO      (SMEM_MISC + 256)
#define SMEM_BYTES   (SMEM_MISC + 832)   // 74560  (x3 CTAs = 223,680)
#define SACC_STRIDE  33

// Weights pre-packed in m16n8k16 A-fragment order, single f16 plane:
// uint4 idx = (step*8 + otile)*32 + lane
__device__ __align__(16) uint32_t g_wAf32[NSTEP * 8 * 32 * 4];   // 294912 B

// Channel-pair + x-pair packed f16 x:
// u64 entry [chpair][i] = { h2(x[c][i], x[c][i+1]), h2(x[c+1][i], x[c+1][i+1]) }
// where c = 2*chpair (global channel). One LDG.64 = 2 channels x 2 x-corners.
__device__ __align__(16) uint2 g_xq[XQ_U64];                     // 33.5 MB

__device__ __forceinline__ uint32_t smem_to_u32(const void* p) {
    uint32_t a;
    asm("{ .reg .u64 t; cvta.to.shared.u64 t, %1; cvt.u32.u64 %0, t; }" : "=r"(a) : "l"(p));
    return a;
}

// S swizzle: row k is 64B (32 px f16), 4 x 16B chunks; chunk ^= (k>>1)&3 so
// ldmatrix's 8-row phases hit disjoint 16B groups.
__device__ __forceinline__ int s_off(int k, int px) {
    return (k << 6) + ((px & 7) << 1) + ((((px >> 3) ^ ((k >> 1) & 3))) << 4);
}

__device__ __forceinline__ void ldsm_x4_trans(uint32_t* r, uint32_t addr) {
    asm volatile("ldmatrix.sync.aligned.m8n8.x4.trans.shared.b16 {%0,%1,%2,%3}, [%4];"
                 : "=r"(r[0]), "=r"(r[1]), "=r"(r[2]), "=r"(r[3]) : "r"(addr));
}
__device__ __forceinline__ void mma_f16(float* c, const uint32_t* a, uint32_t b0, uint32_t b1) {
    asm volatile(
        "mma.sync.aligned.m16n8k16.row.col.f32.f16.f16.f32 "
        "{%0,%1,%2,%3}, {%4,%5,%6,%7}, {%8,%9}, {%0,%1,%2,%3};"
        : "+f"(c[0]), "+f"(c[1]), "+f"(c[2]), "+f"(c[3])
        : "r"(a[0]), "r"(a[1]), "r"(a[2]), "r"(a[3]), "r"(b0), "r"(b1));
}

__device__ __forceinline__ uint32_t pack_h2(float a, float b) {
    __half2 h = __floats2half2_rn(a, b);
    return *reinterpret_cast<uint32_t*>(&h);
}
__device__ __forceinline__ float2 h2f(uint32_t u) {
    return __half22float2(*reinterpret_cast<__half2*>(&u));
}

// ---------------- prep 0: x -> channel-pair/x-pair u64 array ----------------
// thread t covers 4 consecutive i of one channel pair (outputs 4 u64 = 32 B)
__global__ void prep_xq_kernel(const float* __restrict__ x) {
    size_t t  = (size_t)blockIdx.x * 256 + threadIdx.x;   // 1,048,576 threads
    size_t e0 = t * 4;                  // first u64 index
    size_t i  = e0 & (HW - 1);          // i within channel
    size_t cp = e0 >> 14;               // channel pair (global)
    const float* p0 = x + (cp * 2) * (size_t)HW + i;
    const float* p1 = p0 + HW;
    float4 a = *reinterpret_cast<const float4*>(p0);
    float4 c = *reinterpret_cast<const float4*>(p1);
    float an = (i + 4 < HW) ? p0[4] : 0.0f;   // row-crossing pairs never used
    float cn = (i + 4 < HW) ? p1[4] : 0.0f;
    uint4 o0, o1;
    o0.x = pack_h2(a.x, a.y);  o0.y = pack_h2(c.x, c.y);
    o0.z = pack_h2(a.y, a.z);  o0.w = pack_h2(c.y, c.z);
    o1.x = pack_h2(a.z, a.w);  o1.y = pack_h2(c.z, c.w);
    o1.z = pack_h2(a.w, an);   o1.w = pack_h2(c.w, cn);
    uint4* outp = reinterpret_cast<uint4*>(g_xq) + t * 2;
    outp[0] = o0;
    outp[1] = o1;
}

// ---------------- prep: weights -> A-fragment layout, f16 ----------------
__global__ void prep_wAf_kernel(const float* __restrict__ wd) {
    int idx = blockIdx.x * 256 + threadIdx.x;       // b32 index
    if (idx >= NSTEP * 8 * 32 * 4) return;
    int q     = idx & 3;
    int lane  = (idx >> 2) & 31;
    int ot    = (idx >> 7) & 7;
    int step  = idx >> 10;
    int g = lane >> 2, t = lane & 3;
    int row = ot * 16 + g + ((q & 1) << 3);
    int col = step * 16 + t * 2 + ((q >> 1) << 3);
    __half h0 = __float2half_rn(wd[row * RTOT + col]);
    __half h1 = __float2half_rn(wd[row * RTOT + col + 1]);
    g_wAf32[idx] = ((uint32_t)reinterpret_cast<unsigned short&>(h1) << 16)
                 |  (uint32_t)reinterpret_cast<unsigned short&>(h0);
}

// ---------------- main kernel ----------------
__global__ void __launch_bounds__(NTHREADS, 3)
deform_kernel(const float* __restrict__ x,        // unused (g_xq)
              const float* __restrict__ shape,    // [B,2,H,W]
              const float* __restrict__ w_offset, // [72][2]
              float* __restrict__ out)            // [B,COUT,H,W]
{
    extern __shared__ char smem[];
    const uint32_t smem_u32 = smem_to_u32(smem);
    float* ss0  = (float*)(smem + OFF_SS0);
    float* ss1  = (float*)(smem + OFF_SS1);
    float* swo  = (float*)(smem + OFF_SWO);
    float* sacc = (float*)(smem + SMEM_S_OFF);   // alias of S, used after GEMM

    const int tid = threadIdx.x;
    const int wid = tid >> 5;
    const int lid = tid & 31;

    const int b   = blockIdx.x >> 9;
    const int rem = blockIdx.x & 511;
    const int h   = rem >> 2;
    const int w0  = (rem & 3) << 5;

    // ---- stage small tables ----
    if (tid < 32)                     ss0[tid]     = shape[(size_t)(b*2+0)*HW + h*WDIM + w0 + tid];
    else if (tid < 64)                ss1[tid-32]  = shape[(size_t)(b*2+1)*HW + h*WDIM + w0 + (tid-32)];
    else if (tid >= 64 && tid < 208)  swo[tid-64]  = w_offset[tid-64];
    __syncthreads();

    // ---- phase A: sample via u64 pair loads -> f16 swizzled S [1152][32] ----
    for (int i = tid; i < 36 * TPX; i += NTHREADS) {
        int gk = i >> 5, px = i & 31;
        int g  = gk / 9, k = gk - g * 9;
        int ky = k / 3,  kx = k - ky * 3;
        float s0 = ss0[px], s1 = ss1[px];
        float offy = swo[gk*4 + 0] * s0 + swo[gk*4 + 1] * s1;
        float offx = swo[gk*4 + 2] * s0 + swo[gk*4 + 3] * s1;
        float py  = offy + (float)(ky - 1 + h);
        float pxf = offx + (float)(kx - 1 + w0 + px);
        float y0f = floorf(py), x0f = floorf(pxf);
        float fy = py - y0f, fx = pxf - x0f;
        int y0 = (int)y0f, x0 = (int)x0f;

        // per-row y weights (zeroed when row out of bounds)
        float wy0 = (y0     >= 0 && y0     <= 127) ? (1.0f - fy) : 0.0f;
        float wy1 = (y0 + 1 >= 0 && y0 + 1 <= 127) ? fy          : 0.0f;
        int yc0 = min(max(y0,     0), 127);
        int yc1 = min(max(y0 + 1, 0), 127);

        // x-pair weights: one u64 pair at xb covers both x-corners
        int xb = min(max(x0, 0), 126);
        float wl, wr;
        if (x0 >= 0 && x0 <= 126)      { wl = 1.0f - fx; wr = fx;          }
        else if (x0 == -1)             { wl = fx;        wr = 0.0f;        }
        else if (x0 == 127)            { wl = 0.0f;      wr = 1.0f - fx;   }
        else                           { wl = 0.0f;      wr = 0.0f;        }

        float w00 = wy0 * wl, w01 = wy0 * wr;
        float w10 = wy1 * wl, w11 = wy1 * wr;
        int i0 = yc0 * WDIM + xb;
        int i1 = yc1 * WDIM + xb;

        // channel-pair base for this (b, g): chpair = b*64 + g*16
        const uint2* xq = g_xq + ((size_t)(b * 64 + g * 16)) * HW;
        const int r0 = (g * CG) * KTAPS + k;     // r for cg=0; stride 9 per cg
        #pragma unroll 4
        for (int cgp = 0; cgp < 16; cgp++) {
            const uint2* xc = xq + (size_t)cgp * HW;
            uint2 q0 = xc[i0];      // {c even: (x,x+1)}, {c odd: (x,x+1)} row y0
            uint2 q1 = xc[i1];      // same, row y1
            float2 e0 = h2f(q0.x), o0v = h2f(q0.y);
            float2 e1 = h2f(q1.x), o1v = h2f(q1.y);
            float ve = w00 * e0.x + w01 * e0.y + w10 * e1.x + w11 * e1.y;
            float vo = w00 * o0v.x + w01 * o0v.y + w10 * o1v.x + w11 * o1v.y;
            int r  = r0 + (2 * cgp) * KTAPS;
            *(__half*)(smem + SMEM_S_OFF + s_off(r,         px)) = __float2half_rn(ve);
            *(__half*)(smem + SMEM_S_OFF + s_off(r + KTAPS, px)) = __float2half_rn(vo);
        }
    }
    __syncthreads();

    // ---- phase B: 8 warps = 2 k-halves x 4 o-quarters, tile o32 x n32 ----
    const int kw    = wid >> 2;          // k-half
    const int ow    = wid & 3;           // o-quarter (o = ow*32 .. +31)
    const int bkrow = lid & 15;
    const int bsel  = lid >> 4;

    const uint4* gA = reinterpret_cast<const uint4*>(g_wAf32);

    float acc[2][4][4];
    #pragma unroll
    for (int a1 = 0; a1 < 2; a1++)
        #pragma unroll
        for (int a2 = 0; a2 < 4; a2++)
            #pragma unroll
            for (int a3 = 0; a3 < 4; a3++) acc[a1][a2][a3] = 0.0f;

    const int step0 = kw * HSTEP;
    for (int s = 0; s < HSTEP; s++) {
        const int step = step0 + s;

        uint4 A0 = gA[((step * 8 + (ow << 1) + 0) << 5) + lid];
        uint4 A1 = gA[((step * 8 + (ow << 1) + 1) << 5) + lid];

        const int k = (step << 4) + bkrow;
        uint32_t bf[2][4];
        #pragma unroll
        for (int half = 0; half < 2; half++) {
            int bnchk = (half << 1) + bsel;
            int boff  = (k << 6) + (((bnchk ^ ((k >> 1) & 3))) << 4);
            ldsm_x4_trans(bf[half], smem_u32 + SMEM_S_OFF + (uint32_t)boff);
        }

        const uint32_t* a0 = (const uint32_t*)&A0;
        const uint32_t* a1 = (const uint32_t*)&A1;
        mma_f16(acc[0][0], a0, bf[0][0], bf[0][1]);
        mma_f16(acc[0][1], a0, bf[0][2], bf[0][3]);
        mma_f16(acc[0][2], a0, bf[1][0], bf[1][1]);
        mma_f16(acc[0][3], a0, bf[1][2], bf[1][3]);
        mma_f16(acc[1][0], a1, bf[0][0], bf[0][1]);
        mma_f16(acc[1][1], a1, bf[0][2], bf[0][3]);
        mma_f16(acc[1][2], a1, bf[1][0], bf[1][1]);
        mma_f16(acc[1][3], a1, bf[1][2], bf[1][3]);
    }
    __syncthreads();    // all LDSM from S done; S now reusable as sacc

    // ---- reduction: kw==1 dumps partials; kw==0 adds + ReLU + stores ----
    // acc[ot][j] covers n8 tile j at px = j*8
    const int g = lid >> 2, t = lid & 3;
    if (kw == 1) {
        #pragma unroll
        for (int ot = 0; ot < 2; ot++) {
            #pragma unroll
            for (int j = 0; j < 4; j++) {
                int o  = (ow << 5) + (ot << 4) + g;
                int px = (j << 3) + (t << 1);
                sacc[ o      * SACC_STRIDE + px    ] = acc[ot][j][0];
                sacc[ o      * SACC_STRIDE + px + 1] = acc[ot][j][1];
                sacc[(o + 8) * SACC_STRIDE + px    ] = acc[ot][j][2];
                sacc[(o + 8) * SACC_STRIDE + px + 1] = acc[ot][j][3];
            }
        }
    }
    __syncthreads();
    if (kw == 0) {
        #pragma unroll
        for (int ot = 0; ot < 2; ot++) {
            #pragma unroll
            for (int j = 0; j < 4; j++) {
                int o  = (ow << 5) + (ot << 4) + g;
                int px = (j << 3) + (t << 1);
                float* op0 = out + (((size_t)b * COUT + o) << 14) + (h << 7) + w0 + px;
                float* op1 = op0 + ((size_t)8 << 14);   // row o+8
                float2 v0, v1;
                v0.x = fmaxf(acc[ot][j][0] + sacc[ o      * SACC_STRIDE + px    ], 0.0f);
                v0.y = fmaxf(acc[ot][j][1] + sacc[ o      * SACC_STRIDE + px + 1], 0.0f);
                v1.x = fmaxf(acc[ot][j][2] + sacc[(o + 8) * SACC_STRIDE + px    ], 0.0f);
                v1.y = fmaxf(acc[ot][j][3] + sacc[(o + 8) * SACC_STRIDE + px + 1], 0.0f);
                *reinterpret_cast<float2*>(op0) = v0;
                *reinterpret_cast<float2*>(op1) = v1;
            }
        }
    }
}

extern "C" void kernel_launch(void* const* d_in, const int* in_sizes, int n_in,
                              void* d_out, int out_size) {
    const float* x        = (const float*)d_in[0];
    const float* shape    = (const float*)d_in[1];
    const float* w_offset = (const float*)d_in[2];
    const float* w_deform = (const float*)d_in[3];
    float* out = (float*)d_out;

    cudaFuncSetAttribute(deform_kernel,
                         cudaFuncAttributeMaxDynamicSharedMemorySize, SMEM_BYTES);

    prep_xq_kernel<<<(int)((XQ_U64 / 4) / 256), 256>>>(x);
    prep_wAf_kernel<<<(NSTEP * 8 * 32 * 4 + 255) / 256, 256>>>(w_deform);

    const int nblocks = BATCH * HDIM * (WDIM / TPX);   // 2048
    deform_kernel<<<nblocks, NTHREADS, SMEM_BYTES>>>(x, shape, w_offset, out);
}